// round 13
// baseline (speedup 1.0000x reference)
#include <cuda_runtime.h>
#include <cuda_bf16.h>
#include <mma.h>
#include <cstdint>

using namespace nvcuda;

#define BATCH_ 8
#define H_ 64
#define W_ 64
#define L_ 4096
#define DM_ 192
#define E_ 384
#define N_ 16
#define R_ 12
#define XD_ 44
#define ROWS_ (BATCH_*L_)

// ---------------- cp.async helpers ------------------------------------------
__device__ __forceinline__ uint32_t smem_u32(const void* p) {
    uint32_t a;
    asm("{ .reg .u64 t; cvta.to.shared.u64 t, %1; cvt.u32.u64 %0, t; }" : "=r"(a) : "l"(p));
    return a;
}
#define CP_ASYNC16(dst, src, szbytes) \
    asm volatile("cp.async.cg.shared.global [%0], [%1], 16, %2;" \
                 :: "r"(dst), "l"(src), "r"(szbytes))
#define CP_COMMIT() asm volatile("cp.async.commit_group;")
#define CP_WAIT1()  asm volatile("cp.async.wait_group 1;")
#define CP_WAIT0()  asm volatile("cp.async.wait_group 0;")

// ---------------- scratch ----------------------------------------------------
__device__ float g_xz   [(size_t)ROWS_ * 2 * E_];
__device__ float g_ut   [(size_t)ROWS_ * E_];
__device__ float g_xdbl [(size_t)ROWS_ * XD_];
__device__ float g_y    [(size_t)ROWS_ * E_];
__device__ __nv_bfloat16 g_xaug [(size_t)ROWS_ * 2 * DM_];
__device__ __nv_bfloat16 g_uaug [(size_t)ROWS_ * 2 * E_];
__device__ __nv_bfloat16 g_gaug [(size_t)ROWS_ * 2 * E_];
__device__ __nv_bfloat16 g_wina [(size_t)(2*E_) * 2 * DM_];
__device__ __nv_bfloat16 g_wxa  [(size_t)XD_ * 2 * E_];
__device__ __nv_bfloat16 g_woa  [(size_t)DM_ * 2 * E_];

// ---------- fused hi/lo split for all four tensors ---------------------------
#define SPLIT_N0 (ROWS_ * DM_ / 2)
#define SPLIT_N1 (2 * E_ * DM_ / 2)
#define SPLIT_N2 (XD_ * E_ / 2)
#define SPLIT_N3 (DM_ * E_ / 2)
#define SPLIT_B0 ((SPLIT_N0 + 255) / 256)
#define SPLIT_B1 ((SPLIT_N1 + 255) / 256)
#define SPLIT_B2 ((SPLIT_N2 + 255) / 256)
#define SPLIT_B3 ((SPLIT_N3 + 255) / 256)

__device__ __forceinline__ void split_one(const float* __restrict__ src,
                                          __nv_bfloat16* __restrict__ dst,
                                          int K, int idx, int nwork)
{
    if (idx >= nwork) return;
    int r = idx / (K / 2), kk = (idx - r * (K / 2)) * 2;
    const float2 v2 = *reinterpret_cast<const float2*>(src + (size_t)r * K + kk);
    __nv_bfloat16 h0 = __float2bfloat16(v2.x);
    __nv_bfloat16 h1 = __float2bfloat16(v2.y);
    __nv_bfloat16 l0 = __float2bfloat16(v2.x - __bfloat162float(h0));
    __nv_bfloat16 l1 = __float2bfloat16(v2.y - __bfloat162float(h1));
    uint32_t hw = (uint32_t)__bfloat16_as_ushort(h0) | ((uint32_t)__bfloat16_as_ushort(h1) << 16);
    uint32_t lw = (uint32_t)__bfloat16_as_ushort(l0) | ((uint32_t)__bfloat16_as_ushort(l1) << 16);
    size_t base = (size_t)r * 2 * K + kk;
    *reinterpret_cast<uint32_t*>(&dst[base])     = hw;
    *reinterpret_cast<uint32_t*>(&dst[base + K]) = lw;
}

__global__ void split_all(const float* __restrict__ x,   const float* __restrict__ W_in,
                          const float* __restrict__ W_x, const float* __restrict__ W_out)
{
    int blk = blockIdx.x;
    if (blk < SPLIT_B0) {
        split_one(x, g_xaug, DM_, blk * 256 + threadIdx.x, SPLIT_N0);
    } else if (blk < SPLIT_B0 + SPLIT_B1) {
        split_one(W_in, g_wina, DM_, (blk - SPLIT_B0) * 256 + threadIdx.x, SPLIT_N1);
    } else if (blk < SPLIT_B0 + SPLIT_B1 + SPLIT_B2) {
        split_one(W_x, g_wxa, E_, (blk - SPLIT_B0 - SPLIT_B1) * 256 + threadIdx.x, SPLIT_N2);
    } else {
        split_one(W_out, g_woa, E_, (blk - SPLIT_B0 - SPLIT_B1 - SPLIT_B2) * 256 + threadIdx.x, SPLIT_N3);
    }
}

// ============ WMMA bf16 GEMM, logical Kaug=3*K0 over physical [hi|lo] ========
template<int BN, int NW, bool GUARDN>
__global__ __launch_bounds__(NW * 32, (NW == 4 ? 3 : 2)) void wmma_gemm(
    const __nv_bfloat16* __restrict__ Aaug,
    const __nv_bfloat16* __restrict__ Baug,
    float* __restrict__ C, int ldc, int K0, int Nout)
{
    constexpr int BM = 128, BK = 32;
    constexpr int THREADS = NW * 32;
    constexpr int WNC = BN / (NW / 2);
    constexpr int NFRW = WNC / 16;
    constexpr int LDS = BK + 8;
    constexpr int ABYTES = 3 * BM * LDS * 2;
    constexpr int AITER = (BM * 4) / THREADS;
    constexpr int BITER = (BN * 4) / THREADS;

    extern __shared__ __align__(32) char smem_raw[];
    typedef __nv_bfloat16 ARow[BM][LDS];
    typedef __nv_bfloat16 BRow[BN][LDS];
    ARow* sA = reinterpret_cast<ARow*>(smem_raw);
    BRow* sB = reinterpret_cast<BRow*>(smem_raw + ABYTES);

    const int tid  = threadIdx.x;
    const int wid  = tid >> 5;
    const int wy   = wid & 1;
    const int wx   = wid >> 1;
    const int row0 = blockIdx.y * BM;
    const int col0 = blockIdx.x * BN;
    const int strideAB = 2 * K0;

    wmma::fragment<wmma::accumulator, 16, 16, 16, float> acc[4][NFRW];
    #pragma unroll
    for (int i = 0; i < 4; i++)
        #pragma unroll
        for (int j = 0; j < NFRW; j++) wmma::fill_fragment(acc[i][j], 0.f);

    const int nk = (3 * K0) / BK;

    auto ld_tiles = [&](int kc, int buf) {
        const int p    = kc * BK;
        const int aOff = (p < 2 * K0) ? p : p - 2 * K0;
        const int bOff = (p < K0)     ? p : p - K0;
        #pragma unroll
        for (int it = 0; it < AITER; it++) {
            int idx = it * THREADS + tid;
            int r = idx >> 2, ck = idx & 3;
            const __nv_bfloat16* src = Aaug + (size_t)(row0 + r) * strideAB + aOff + ck * 8;
            CP_ASYNC16(smem_u32(&sA[buf][r][ck * 8]), src, 16);
        }
        #pragma unroll
        for (int it = 0; it < BITER; it++) {
            int idx = it * THREADS + tid;
            int r = idx >> 2, ck = idx & 3;
            int n = col0 + r;
            const __nv_bfloat16* src = Baug + (size_t)n * strideAB + bOff + ck * 8;
            CP_ASYNC16(smem_u32(&sB[buf][r][ck * 8]), src, (!GUARDN || n < Nout) ? 16 : 0);
        }
    };

    auto compute = [&](int buf) {
        #pragma unroll
        for (int ks = 0; ks < 2; ks++) {
            wmma::fragment<wmma::matrix_b, 16, 16, 16, __nv_bfloat16, wmma::col_major> bf[NFRW];
            #pragma unroll
            for (int j = 0; j < NFRW; j++)
                wmma::load_matrix_sync(bf[j], &sB[buf][wx * WNC + j * 16][ks * 16], LDS);
            #pragma unroll
            for (int i = 0; i < 4; i++) {
                wmma::fragment<wmma::matrix_a, 16, 16, 16, __nv_bfloat16, wmma::row_major> af;
                wmma::load_matrix_sync(af, &sA[buf][wy * 64 + i * 16][ks * 16], LDS);
                #pragma unroll
                for (int j = 0; j < NFRW; j++)
                    wmma::mma_sync(acc[i][j], af, bf[j], acc[i][j]);
            }
        }
    };

    ld_tiles(0, 0); CP_COMMIT();
    ld_tiles(1, 1); CP_COMMIT();

    for (int kt = 0; kt < nk; kt++) {
        const int buf = kt % 3;
        if (kt + 1 < nk) { CP_WAIT1(); } else { CP_WAIT0(); }
        __syncthreads();
        if (kt + 2 < nk) { ld_tiles(kt + 2, (kt + 2) % 3); CP_COMMIT(); }
        compute(buf);
    }

    if (!GUARDN) {
        #pragma unroll
        for (int i = 0; i < 4; i++)
            #pragma unroll
            for (int j = 0; j < NFRW; j++) {
                int cc = col0 + wx * WNC + j * 16;
                if (cc + 16 <= Nout)
                    wmma::store_matrix_sync(
                        C + (size_t)(row0 + wy * 64 + i * 16) * ldc + cc,
                        acc[i][j], ldc, wmma::mem_row_major);
            }
    } else {
        float* stage = reinterpret_cast<float*>(smem_raw);
        __syncthreads();
        #pragma unroll
        for (int i = 0; i < 4; i++)
            #pragma unroll
            for (int j = 0; j < NFRW; j++)
                wmma::store_matrix_sync(
                    stage + (size_t)(wy * 64 + i * 16) * BN + wx * WNC + j * 16,
                    acc[i][j], BN, wmma::mem_row_major);
        __syncthreads();
        for (int idx = tid; idx < BM * BN; idx += THREADS) {
            int r = idx / BN, c = idx - r * BN;
            if (col0 + c < Nout)
                C[(size_t)(row0 + r) * ldc + col0 + c] = stage[idx];
        }
    }
}

// ============ depthwise 7x7 conv + SiLU — sliding 7-deep accumulator =========
__global__ __launch_bounds__(128) void dwconv_silu(
    const float* __restrict__ xz, const float* __restrict__ cw,
    const float* __restrict__ cb, float* __restrict__ u_t,
    __nv_bfloat16* __restrict__ uaug)
{
    const int tid = threadIdx.x;
    const int e   = blockIdx.x * 128 + tid;
    const int ty0 = (blockIdx.y >> 3) * 8;
    const int tx0 = (blockIdx.y & 7) * 8;
    const int b   = blockIdx.z;

    __shared__ float wsh[128 * 49];
    for (int i = tid; i < 128 * 49; i += 128)
        wsh[i] = cw[(size_t)blockIdx.x * 128 * 49 + i];
    __syncthreads();
    float wr[49];
    #pragma unroll
    for (int j = 0; j < 49; j++) wr[j] = wsh[tid * 49 + j];
    const float bv = cb[e];

    float acc[7][8];
    #pragma unroll
    for (int j = 0; j < 7; j++)
        #pragma unroll
        for (int ox = 0; ox < 8; ox++) acc[j][ox] = bv;

    const size_t rowbase = (size_t)b * L_;
    float* utbase = u_t + ((size_t)b * E_ + e) * L_;

    #pragma unroll 1
    for (int iy = ty0 - 3; iy <= ty0 + 10; iy++) {
        if (iy >= 0 && iy < H_) {
            float row[14];
            const float* rp = xz + (rowbase + (size_t)iy * W_) * (2 * E_) + e;
            #pragma unroll
            for (int c = 0; c < 14; c++) {
                const int ix = tx0 + c - 3;
                row[c] = (ix >= 0 && ix < W_) ? rp[(size_t)ix * (2 * E_)] : 0.f;
            }
            #pragma unroll
            for (int ky = 0; ky < 7; ky++) {
                const int yy = iy + 3 - ky;
                if (yy >= ty0 && yy < ty0 + 8) {
                    #pragma unroll
                    for (int kx = 0; kx < 7; kx++) {
                        const float wv = wr[ky * 7 + kx];
                        #pragma unroll
                        for (int ox = 0; ox < 8; ox++)
                            acc[6 - ky][ox] = fmaf(row[ox + kx], wv, acc[6 - ky][ox]);
                    }
                }
            }
        }
        const int yy = iy - 3;
        if (yy >= ty0 && yy < ty0 + 8) {
            float v[8];
            #pragma unroll
            for (int ox = 0; ox < 8; ox++) {
                const float a0 = acc[0][ox];
                v[ox] = a0 / (1.f + __expf(-a0));
                const size_t row_t = rowbase + yy * W_ + tx0 + ox;
                __nv_bfloat16 hi = __float2bfloat16(v[ox]);
                __nv_bfloat16 lo = __float2bfloat16(v[ox] - __bfloat162float(hi));
                const size_t ab = row_t * (2 * E_) + e;
                uaug[ab] = hi; uaug[ab + E_] = lo;
            }
            float4* up = reinterpret_cast<float4*>(utbase + yy * W_ + tx0);
            up[0] = make_float4(v[0], v[1], v[2], v[3]);
            up[1] = make_float4(v[4], v[5], v[6], v[7]);
        }
        #pragma unroll
        for (int j = 0; j < 6; j++)
            #pragma unroll
            for (int ox = 0; ox < 8; ox++) acc[j][ox] = acc[j + 1][ox];
        #pragma unroll
        for (int ox = 0; ox < 8; ox++) acc[6][ox] = bv;
    }
}

// ============ selective scan — fused delta + smem-staged xdbl ================
// block = 4 warps = same b, 8 consecutive e's. Per 16-step chunk:
//  - xdbl rows staged in smem (double-buffered, prefetch during compute)
//  - delta computed lane-parallel (lane = (t 0..15) x (e-half)), softplus once
//  - coalesced y flush via ybuf. ONE __syncthreads per chunk.
#define XP_ 45   // padded row stride for xsh
__global__ __launch_bounds__(128) void scan_kernel(
    const float* __restrict__ u_t,  const float* __restrict__ xdbl,
    const float* __restrict__ W_dt, const float* __restrict__ b_dt,
    const float* __restrict__ A_log, const float* __restrict__ Dp,
    float* __restrict__ y)
{
    __shared__ float xsh[2][16][XP_];
    __shared__ float ybuf[2][16][8];

    const int tid  = threadIdx.x;
    const int wl   = tid >> 5;
    const int lane = tid & 31;
    const int half = lane >> 4;
    const int n    = lane & 15;
    const int gw   = blockIdx.x * 4 + wl;
    const int b    = gw / (E_ / 2);
    const int e    = (gw % (E_ / 2)) * 2 + half;
    const int e0   = (blockIdx.x % 48) * 8;

    const float a  = -__expf(A_log[e * N_ + n]);
    const float dp = Dp[e];
    const float b2 = 2.f * b_dt[e];
    float wdt[R_];
    #pragma unroll
    for (int k = 0; k < R_; k++) wdt[k] = W_dt[e * R_ + k];
    float s = 0.f;

    const float* uptr = u_t  + ((size_t)b * E_ + e) * L_;
    const float* xrow = xdbl + (size_t)b * L_ * XD_;
    float* yblk = y + ((size_t)b * L_) * E_ + e0;

    const int tl_st = tid >> 3;
    const int el_st = tid & 7;

    // preload chunk 0
    for (int i = tid; i < 16 * XD_; i += 128) {
        int rr = i / XD_, cc = i - rr * XD_;
        xsh[0][rr][cc] = xrow[(size_t)rr * XD_ + cc];
    }
    __syncthreads();

    int p = 0;
    for (int c = 0; c < L_ / 16; c++) {
        const int t0 = c * 16;
        // prefetch next chunk into xsh[p^1]
        if (c + 1 < L_ / 16) {
            for (int i = tid; i < 16 * XD_; i += 128) {
                int rr = i / XD_, cc = i - rr * XD_;
                xsh[p ^ 1][rr][cc] = xrow[(size_t)(t0 + 16 + rr) * XD_ + cc];
            }
        }
        // lane-parallel delta: lane handles t-row n, its own e
        float dval = b2;
        #pragma unroll
        for (int k = 0; k < R_; k++) dval = fmaf(xsh[p][n][k], wdt[k], dval);
        const float dlt = (dval > 20.f) ? dval : log1pf(__expf(dval));

        #pragma unroll
        for (int sb = 0; sb < 2; sb++) {
            const int tb = t0 + sb * 8;
            float uv[8], v[8];
            #pragma unroll
            for (int h = 0; h < 2; h++) {
                const float4 u4 = *reinterpret_cast<const float4*>(uptr + tb + 4 * h);
                uv[4*h] = u4.x; uv[4*h+1] = u4.y; uv[4*h+2] = u4.z; uv[4*h+3] = u4.w;
            }
            float d[8], ex[8];
            #pragma unroll
            for (int q = 0; q < 8; q++) {
                d[q]  = __shfl_sync(0xffffffffu, dlt, (half << 4) | (sb * 8 + q));
                ex[q] = __expf(d[q] * a);
            }
            #pragma unroll
            for (int q = 0; q < 8; q++) {
                const int idx = sb * 8 + q;
                const float Bn = xsh[p][idx][R_ + n];
                const float Cn = xsh[p][idx][R_ + N_ + n];
                s = fmaf(s, ex[q], (d[q] * uv[q]) * Bn);
                v[q] = s * Cn;
            }
            #pragma unroll
            for (int q = 0; q < 8; q++) {
                v[q] += __shfl_xor_sync(0xffffffffu, v[q], 1);
                v[q] += __shfl_xor_sync(0xffffffffu, v[q], 2);
                v[q] += __shfl_xor_sync(0xffffffffu, v[q], 4);
                v[q] += __shfl_xor_sync(0xffffffffu, v[q], 8);
            }
            if (n == 0) {
                #pragma unroll
                for (int q = 0; q < 8; q++)
                    ybuf[p][sb * 8 + q][wl * 2 + half] = fmaf(uv[q], dp, v[q]);
            }
        }
        __syncthreads();
        yblk[(size_t)(t0 + tl_st) * E_ + el_st] = ybuf[p][tl_st][el_st];
        p ^= 1;
    }
}

// ============ batch-sum + gate -> g_aug [hi|lo] ===============================
__global__ __launch_bounds__(256) void gate_kernel(
    const float4* __restrict__ y4, const float* __restrict__ xz,
    __nv_bfloat16* __restrict__ gaug)
{
    const int idx = blockIdx.x * blockDim.x + threadIdx.x;
    if (idx >= L_ * E_ / 4) return;
    float4 ss = make_float4(0.f, 0.f, 0.f, 0.f);
    #pragma unroll
    for (int b = 0; b < BATCH_; b++) {
        const float4 t = y4[(size_t)b * (L_ * E_ / 4) + idx];
        ss.x += t.x; ss.y += t.y; ss.z += t.z; ss.w += t.w;
    }
    const int p = idx * 4;
    const int t = p / E_;
    const int e = p - t * E_;
    #pragma unroll
    for (int b = 0; b < BATCH_; b++) {
        const float4 z4 = *reinterpret_cast<const float4*>(
            xz + ((size_t)(b * L_ + t)) * (2 * E_) + E_ + e);
        float v[4];
        v[0] = ss.x * z4.x / (1.f + __expf(-z4.x));
        v[1] = ss.y * z4.y / (1.f + __expf(-z4.y));
        v[2] = ss.z * z4.z / (1.f + __expf(-z4.z));
        v[3] = ss.w * z4.w / (1.f + __expf(-z4.w));
        uint32_t hiw[2], low[2];
        #pragma unroll
        for (int h = 0; h < 2; h++) {
            __nv_bfloat16 h0 = __float2bfloat16(v[2*h]);
            __nv_bfloat16 h1 = __float2bfloat16(v[2*h+1]);
            __nv_bfloat16 l0 = __float2bfloat16(v[2*h]   - __bfloat162float(h0));
            __nv_bfloat16 l1 = __float2bfloat16(v[2*h+1] - __bfloat162float(h1));
            hiw[h] = (uint32_t)__bfloat16_as_ushort(h0) |
                     ((uint32_t)__bfloat16_as_ushort(h1) << 16);
            low[h] = (uint32_t)__bfloat16_as_ushort(l0) |
                     ((uint32_t)__bfloat16_as_ushort(l1) << 16);
        }
        const size_t base = ((size_t)(b * L_ + t)) * (2 * E_) + e;
        *reinterpret_cast<uint2*>(&gaug[base])      = make_uint2(hiw[0], hiw[1]);
        *reinterpret_cast<uint2*>(&gaug[base + E_]) = make_uint2(low[0], low[1]);
    }
}

// ============ launch ==========================================================
extern "C" void kernel_launch(void* const* d_in, const int* in_sizes, int n_in,
                              void* d_out, int out_size)
{
    int base = 3;
    if (in_sizes[1] == 2 * E_ * DM_) base = 1;

    const float* x      = (const float*)d_in[0];
    const float* W_in   = (const float*)d_in[base + 0];
    const float* conv_w = (const float*)d_in[base + 1];
    const float* conv_b = (const float*)d_in[base + 2];
    const float* W_x    = (const float*)d_in[base + 3];
    const float* W_dt   = (const float*)d_in[base + 4];
    const float* b_dt   = (const float*)d_in[base + 5];
    const float* A_log  = (const float*)d_in[base + 6];
    const float* Dp     = (const float*)d_in[base + 7];
    const float* W_out  = (const float*)d_in[base + 8];
    float* out = (float*)d_out;

    float *xz, *ut, *xdbl, *y;
    __nv_bfloat16 *xaug, *uaug, *gaug, *wina, *wxa, *woa;
    cudaGetSymbolAddress((void**)&xz,    g_xz);
    cudaGetSymbolAddress((void**)&ut,    g_ut);
    cudaGetSymbolAddress((void**)&xdbl,  g_xdbl);
    cudaGetSymbolAddress((void**)&y,     g_y);
    cudaGetSymbolAddress((void**)&xaug,  g_xaug);
    cudaGetSymbolAddress((void**)&uaug,  g_uaug);
    cudaGetSymbolAddress((void**)&gaug,  g_gaug);
    cudaGetSymbolAddress((void**)&wina,  g_wina);
    cudaGetSymbolAddress((void**)&wxa,   g_wxa);
    cudaGetSymbolAddress((void**)&woa,   g_woa);

    // dynamic smem (LDS=40: 80B rows)
    const int sz128 = 3 * 128 * 40 * 2 + 3 * 128 * 40 * 2;  // 61440 (BN=128)
    const int sz96  = 3 * 128 * 40 * 2 + 3 *  96 * 40 * 2;  // 53760 (BN=96)
    const int sz64a = 3 * 128 * 40 * 2 + 3 *  64 * 40 * 2;  // 46080 (BN=64)
    const int sz64  = sz64a > 128 * 64 * 4 ? sz64a : 128 * 64 * 4;
    cudaFuncSetAttribute(wmma_gemm<128, 4, false>, cudaFuncAttributeMaxDynamicSharedMemorySize, sz128);
    cudaFuncSetAttribute(wmma_gemm<96, 4, false>,  cudaFuncAttributeMaxDynamicSharedMemorySize, sz96);
    cudaFuncSetAttribute(wmma_gemm<64, 8, true>,   cudaFuncAttributeMaxDynamicSharedMemorySize, sz64);

    // order: split(0), GEMM1(1), conv(2), GEMM3(3=profiled), scan(4), gate(5), GEMM7(6)
    split_all<<<SPLIT_B0 + SPLIT_B1 + SPLIT_B2 + SPLIT_B3, 256>>>(x, W_in, W_x, W_out);
    wmma_gemm<128, 4, false><<<dim3(6, ROWS_ / 128), 128, sz128>>>(
        xaug, wina, xz, 2 * E_, DM_, 2 * E_);
    dwconv_silu<<<dim3(3, 64, BATCH_), 128>>>(xz, conv_w, conv_b, ut, uaug);
    wmma_gemm<64, 8, true><<<dim3(1, ROWS_ / 128), 256, sz64>>>(
        uaug, wxa, xdbl, XD_, E_, XD_);
    scan_kernel<<<BATCH_ * (E_ / 2) / 4, 128>>>(ut, xdbl, W_dt, b_dt, A_log, Dp, y);
    gate_kernel<<<(L_ * E_ / 4 + 255) / 256, 256>>>(
        reinterpret_cast<const float4*>(y), xz, gaug);
    wmma_gemm<96, 4, false><<<dim3(2, ROWS_ / 128), 128, sz96>>>(
        gaug, woa, out, DM_, E_, DM_);
}

// round 14
// speedup vs baseline: 1.3744x; 1.3744x over previous
#include <cuda_runtime.h>
#include <cuda_bf16.h>
#include <mma.h>
#include <cstdint>

using namespace nvcuda;

#define BATCH_ 8
#define H_ 64
#define W_ 64
#define L_ 4096
#define DM_ 192
#define E_ 384
#define N_ 16
#define R_ 12
#define XD_ 44
#define ROWS_ (BATCH_*L_)

// ---------------- cp.async helpers ------------------------------------------
__device__ __forceinline__ uint32_t smem_u32(const void* p) {
    uint32_t a;
    asm("{ .reg .u64 t; cvta.to.shared.u64 t, %1; cvt.u32.u64 %0, t; }" : "=r"(a) : "l"(p));
    return a;
}
#define CP_ASYNC16(dst, src, szbytes) \
    asm volatile("cp.async.cg.shared.global [%0], [%1], 16, %2;" \
                 :: "r"(dst), "l"(src), "r"(szbytes))
#define CP_COMMIT() asm volatile("cp.async.commit_group;")
#define CP_WAIT1()  asm volatile("cp.async.wait_group 1;")
#define CP_WAIT0()  asm volatile("cp.async.wait_group 0;")

// ---------------- scratch ----------------------------------------------------
__device__ float g_xz   [(size_t)ROWS_ * 2 * E_];
__device__ float g_ut   [(size_t)ROWS_ * E_];
__device__ float g_xdbl [(size_t)ROWS_ * XD_];
__device__ float g_y    [(size_t)ROWS_ * E_];
__device__ __nv_bfloat16 g_xaug [(size_t)ROWS_ * 2 * DM_];
__device__ __nv_bfloat16 g_uaug [(size_t)ROWS_ * 2 * E_];
__device__ __nv_bfloat16 g_gaug [(size_t)ROWS_ * 2 * E_];
__device__ __nv_bfloat16 g_wina [(size_t)(2*E_) * 2 * DM_];
__device__ __nv_bfloat16 g_wxa  [(size_t)XD_ * 2 * E_];
__device__ __nv_bfloat16 g_woa  [(size_t)DM_ * 2 * E_];

// ---------- fused hi/lo split for all four tensors ---------------------------
#define SPLIT_N0 (ROWS_ * DM_ / 2)
#define SPLIT_N1 (2 * E_ * DM_ / 2)
#define SPLIT_N2 (XD_ * E_ / 2)
#define SPLIT_N3 (DM_ * E_ / 2)
#define SPLIT_B0 ((SPLIT_N0 + 255) / 256)
#define SPLIT_B1 ((SPLIT_N1 + 255) / 256)
#define SPLIT_B2 ((SPLIT_N2 + 255) / 256)
#define SPLIT_B3 ((SPLIT_N3 + 255) / 256)

__device__ __forceinline__ void split_one(const float* __restrict__ src,
                                          __nv_bfloat16* __restrict__ dst,
                                          int K, int idx, int nwork)
{
    if (idx >= nwork) return;
    int r = idx / (K / 2), kk = (idx - r * (K / 2)) * 2;
    const float2 v2 = *reinterpret_cast<const float2*>(src + (size_t)r * K + kk);
    __nv_bfloat16 h0 = __float2bfloat16(v2.x);
    __nv_bfloat16 h1 = __float2bfloat16(v2.y);
    __nv_bfloat16 l0 = __float2bfloat16(v2.x - __bfloat162float(h0));
    __nv_bfloat16 l1 = __float2bfloat16(v2.y - __bfloat162float(h1));
    uint32_t hw = (uint32_t)__bfloat16_as_ushort(h0) | ((uint32_t)__bfloat16_as_ushort(h1) << 16);
    uint32_t lw = (uint32_t)__bfloat16_as_ushort(l0) | ((uint32_t)__bfloat16_as_ushort(l1) << 16);
    size_t base = (size_t)r * 2 * K + kk;
    *reinterpret_cast<uint32_t*>(&dst[base])     = hw;
    *reinterpret_cast<uint32_t*>(&dst[base + K]) = lw;
}

__global__ void split_all(const float* __restrict__ x,   const float* __restrict__ W_in,
                          const float* __restrict__ W_x, const float* __restrict__ W_out)
{
    int blk = blockIdx.x;
    if (blk < SPLIT_B0) {
        split_one(x, g_xaug, DM_, blk * 256 + threadIdx.x, SPLIT_N0);
    } else if (blk < SPLIT_B0 + SPLIT_B1) {
        split_one(W_in, g_wina, DM_, (blk - SPLIT_B0) * 256 + threadIdx.x, SPLIT_N1);
    } else if (blk < SPLIT_B0 + SPLIT_B1 + SPLIT_B2) {
        split_one(W_x, g_wxa, E_, (blk - SPLIT_B0 - SPLIT_B1) * 256 + threadIdx.x, SPLIT_N2);
    } else {
        split_one(W_out, g_woa, E_, (blk - SPLIT_B0 - SPLIT_B1 - SPLIT_B2) * 256 + threadIdx.x, SPLIT_N3);
    }
}

// ============ WMMA bf16 GEMM, logical Kaug=3*K0 over physical [hi|lo] ========
template<int BN, int NW, bool GUARDN>
__global__ __launch_bounds__(NW * 32, (NW == 4 ? 3 : 2)) void wmma_gemm(
    const __nv_bfloat16* __restrict__ Aaug,
    const __nv_bfloat16* __restrict__ Baug,
    float* __restrict__ C, int ldc, int K0, int Nout)
{
    constexpr int BM = 128, BK = 32;
    constexpr int THREADS = NW * 32;
    constexpr int WNC = BN / (NW / 2);
    constexpr int NFRW = WNC / 16;
    constexpr int LDS = BK + 8;
    constexpr int ABYTES = 3 * BM * LDS * 2;
    constexpr int AITER = (BM * 4) / THREADS;
    constexpr int BITER = (BN * 4) / THREADS;

    extern __shared__ __align__(32) char smem_raw[];
    typedef __nv_bfloat16 ARow[BM][LDS];
    typedef __nv_bfloat16 BRow[BN][LDS];
    ARow* sA = reinterpret_cast<ARow*>(smem_raw);
    BRow* sB = reinterpret_cast<BRow*>(smem_raw + ABYTES);

    const int tid  = threadIdx.x;
    const int wid  = tid >> 5;
    const int wy   = wid & 1;
    const int wx   = wid >> 1;
    const int row0 = blockIdx.y * BM;
    const int col0 = blockIdx.x * BN;
    const int strideAB = 2 * K0;

    wmma::fragment<wmma::accumulator, 16, 16, 16, float> acc[4][NFRW];
    #pragma unroll
    for (int i = 0; i < 4; i++)
        #pragma unroll
        for (int j = 0; j < NFRW; j++) wmma::fill_fragment(acc[i][j], 0.f);

    const int nk = (3 * K0) / BK;

    auto ld_tiles = [&](int kc, int buf) {
        const int p    = kc * BK;
        const int aOff = (p < 2 * K0) ? p : p - 2 * K0;
        const int bOff = (p < K0)     ? p : p - K0;
        #pragma unroll
        for (int it = 0; it < AITER; it++) {
            int idx = it * THREADS + tid;
            int r = idx >> 2, ck = idx & 3;
            const __nv_bfloat16* src = Aaug + (size_t)(row0 + r) * strideAB + aOff + ck * 8;
            CP_ASYNC16(smem_u32(&sA[buf][r][ck * 8]), src, 16);
        }
        #pragma unroll
        for (int it = 0; it < BITER; it++) {
            int idx = it * THREADS + tid;
            int r = idx >> 2, ck = idx & 3;
            int n = col0 + r;
            const __nv_bfloat16* src = Baug + (size_t)n * strideAB + bOff + ck * 8;
            CP_ASYNC16(smem_u32(&sB[buf][r][ck * 8]), src, (!GUARDN || n < Nout) ? 16 : 0);
        }
    };

    auto compute = [&](int buf) {
        #pragma unroll
        for (int ks = 0; ks < 2; ks++) {
            wmma::fragment<wmma::matrix_b, 16, 16, 16, __nv_bfloat16, wmma::col_major> bf[NFRW];
            #pragma unroll
            for (int j = 0; j < NFRW; j++)
                wmma::load_matrix_sync(bf[j], &sB[buf][wx * WNC + j * 16][ks * 16], LDS);
            #pragma unroll
            for (int i = 0; i < 4; i++) {
                wmma::fragment<wmma::matrix_a, 16, 16, 16, __nv_bfloat16, wmma::row_major> af;
                wmma::load_matrix_sync(af, &sA[buf][wy * 64 + i * 16][ks * 16], LDS);
                #pragma unroll
                for (int j = 0; j < NFRW; j++)
                    wmma::mma_sync(acc[i][j], af, bf[j], acc[i][j]);
            }
        }
    };

    ld_tiles(0, 0); CP_COMMIT();
    ld_tiles(1, 1); CP_COMMIT();

    for (int kt = 0; kt < nk; kt++) {
        const int buf = kt % 3;
        if (kt + 1 < nk) { CP_WAIT1(); } else { CP_WAIT0(); }
        __syncthreads();
        if (kt + 2 < nk) { ld_tiles(kt + 2, (kt + 2) % 3); CP_COMMIT(); }
        compute(buf);
    }

    if (!GUARDN) {
        #pragma unroll
        for (int i = 0; i < 4; i++)
            #pragma unroll
            for (int j = 0; j < NFRW; j++) {
                int cc = col0 + wx * WNC + j * 16;
                if (cc + 16 <= Nout)
                    wmma::store_matrix_sync(
                        C + (size_t)(row0 + wy * 64 + i * 16) * ldc + cc,
                        acc[i][j], ldc, wmma::mem_row_major);
            }
    } else {
        float* stage = reinterpret_cast<float*>(smem_raw);
        __syncthreads();
        #pragma unroll
        for (int i = 0; i < 4; i++)
            #pragma unroll
            for (int j = 0; j < NFRW; j++)
                wmma::store_matrix_sync(
                    stage + (size_t)(wy * 64 + i * 16) * BN + wx * WNC + j * 16,
                    acc[i][j], BN, wmma::mem_row_major);
        __syncthreads();
        for (int idx = tid; idx < BM * BN; idx += THREADS) {
            int r = idx / BN, c = idx - r * BN;
            if (col0 + c < Nout)
                C[(size_t)(row0 + r) * ldc + col0 + c] = stage[idx];
        }
    }
}

// ============ depthwise 7x7 conv + SiLU — sliding 7-deep accumulator =========
__global__ __launch_bounds__(128) void dwconv_silu(
    const float* __restrict__ xz, const float* __restrict__ cw,
    const float* __restrict__ cb, float* __restrict__ u_t,
    __nv_bfloat16* __restrict__ uaug)
{
    const int tid = threadIdx.x;
    const int e   = blockIdx.x * 128 + tid;
    const int ty0 = (blockIdx.y >> 3) * 8;
    const int tx0 = (blockIdx.y & 7) * 8;
    const int b   = blockIdx.z;

    __shared__ float wsh[128 * 49];
    for (int i = tid; i < 128 * 49; i += 128)
        wsh[i] = cw[(size_t)blockIdx.x * 128 * 49 + i];
    __syncthreads();
    float wr[49];
    #pragma unroll
    for (int j = 0; j < 49; j++) wr[j] = wsh[tid * 49 + j];
    const float bv = cb[e];

    float acc[7][8];
    #pragma unroll
    for (int j = 0; j < 7; j++)
        #pragma unroll
        for (int ox = 0; ox < 8; ox++) acc[j][ox] = bv;

    const size_t rowbase = (size_t)b * L_;
    float* utbase = u_t + ((size_t)b * E_ + e) * L_;

    #pragma unroll 1
    for (int iy = ty0 - 3; iy <= ty0 + 10; iy++) {
        if (iy >= 0 && iy < H_) {
            float row[14];
            const float* rp = xz + (rowbase + (size_t)iy * W_) * (2 * E_) + e;
            #pragma unroll
            for (int c = 0; c < 14; c++) {
                const int ix = tx0 + c - 3;
                row[c] = (ix >= 0 && ix < W_) ? rp[(size_t)ix * (2 * E_)] : 0.f;
            }
            #pragma unroll
            for (int ky = 0; ky < 7; ky++) {
                const int yy = iy + 3 - ky;
                if (yy >= ty0 && yy < ty0 + 8) {
                    #pragma unroll
                    for (int kx = 0; kx < 7; kx++) {
                        const float wv = wr[ky * 7 + kx];
                        #pragma unroll
                        for (int ox = 0; ox < 8; ox++)
                            acc[6 - ky][ox] = fmaf(row[ox + kx], wv, acc[6 - ky][ox]);
                    }
                }
            }
        }
        const int yy = iy - 3;
        if (yy >= ty0 && yy < ty0 + 8) {
            float v[8];
            #pragma unroll
            for (int ox = 0; ox < 8; ox++) {
                const float a0 = acc[0][ox];
                v[ox] = a0 / (1.f + __expf(-a0));
                const size_t row_t = rowbase + yy * W_ + tx0 + ox;
                __nv_bfloat16 hi = __float2bfloat16(v[ox]);
                __nv_bfloat16 lo = __float2bfloat16(v[ox] - __bfloat162float(hi));
                const size_t ab = row_t * (2 * E_) + e;
                uaug[ab] = hi; uaug[ab + E_] = lo;
            }
            float4* up = reinterpret_cast<float4*>(utbase + yy * W_ + tx0);
            up[0] = make_float4(v[0], v[1], v[2], v[3]);
            up[1] = make_float4(v[4], v[5], v[6], v[7]);
        }
        #pragma unroll
        for (int j = 0; j < 6; j++)
            #pragma unroll
            for (int ox = 0; ox < 8; ox++) acc[j][ox] = acc[j + 1][ox];
        #pragma unroll
        for (int ox = 0; ox < 8; ox++) acc[6][ox] = bv;
    }
}

// ============ selective scan — fused delta, cp.async-staged xdbl =============
// block = 4 warps = same b, 8 consecutive e's. Per 16-step chunk:
//  - xdbl rows prefetched via cp.async (latency hidden behind compute)
//  - delta computed lane-parallel, softplus once per (t,e)
//  - coalesced y flush via ybuf. ONE __syncthreads per chunk.
#define XP_ 44   // row stride (floats); 176B = 11 x 16B (cp.async-aligned)
__global__ __launch_bounds__(128) void scan_kernel(
    const float* __restrict__ u_t,  const float* __restrict__ xdbl,
    const float* __restrict__ W_dt, const float* __restrict__ b_dt,
    const float* __restrict__ A_log, const float* __restrict__ Dp,
    float* __restrict__ y)
{
    __shared__ __align__(16) float xsh[2][16][XP_];
    __shared__ float ybuf[2][16][8];

    const int tid  = threadIdx.x;
    const int wl   = tid >> 5;
    const int lane = tid & 31;
    const int half = lane >> 4;
    const int n    = lane & 15;
    const int gw   = blockIdx.x * 4 + wl;
    const int b    = gw / (E_ / 2);
    const int e    = (gw % (E_ / 2)) * 2 + half;
    const int e0   = (blockIdx.x % 48) * 8;

    const float a  = -__expf(A_log[e * N_ + n]);
    const float dp = Dp[e];
    const float b2 = 2.f * b_dt[e];
    float wdt[R_];
    #pragma unroll
    for (int k = 0; k < R_; k++) wdt[k] = W_dt[e * R_ + k];
    float s = 0.f;

    const float* uptr = u_t  + ((size_t)b * E_ + e) * L_;
    const float* xrow = xdbl + (size_t)b * L_ * XD_;
    float* yblk = y + ((size_t)b * L_) * E_ + e0;

    const int tl_st = tid >> 3;
    const int el_st = tid & 7;

    // cp.async stage of one 16-row chunk: 16 rows x 11 x 16B = 176 ops
    auto stage = [&](int t0, int buf) {
        if (tid < 176 - 128 || true) {
            // two strided passes over 176 items with 128 threads
            #pragma unroll
            for (int it = 0; it < 2; it++) {
                int idx = it * 128 + tid;
                if (idx < 176) {
                    int rr = idx / 11, cc = idx - rr * 11;
                    const float* src = xrow + (size_t)(t0 + rr) * XD_ + cc * 4;
                    CP_ASYNC16(smem_u32(&xsh[buf][rr][cc * 4]), src, 16);
                }
            }
        }
    };

    stage(0, 0); CP_COMMIT(); CP_WAIT0();
    __syncthreads();

    int p = 0;
    for (int c = 0; c < L_ / 16; c++) {
        const int t0 = c * 16;
        // async prefetch next chunk (latency hidden behind this chunk's compute)
        if (c + 1 < L_ / 16) { stage(t0 + 16, p ^ 1); CP_COMMIT(); }

        // lane-parallel delta: lane handles t-row n, its own e
        float dval = b2;
        #pragma unroll
        for (int k = 0; k < R_; k++) dval = fmaf(xsh[p][n][k], wdt[k], dval);
        const float dlt = (dval > 20.f) ? dval : log1pf(__expf(dval));

        #pragma unroll
        for (int sb = 0; sb < 2; sb++) {
            const int tb = t0 + sb * 8;
            float uv[8], v[8];
            #pragma unroll
            for (int h = 0; h < 2; h++) {
                const float4 u4 = *reinterpret_cast<const float4*>(uptr + tb + 4 * h);
                uv[4*h] = u4.x; uv[4*h+1] = u4.y; uv[4*h+2] = u4.z; uv[4*h+3] = u4.w;
            }
            float d[8], ex[8];
            #pragma unroll
            for (int q = 0; q < 8; q++) {
                d[q]  = __shfl_sync(0xffffffffu, dlt, (half << 4) | (sb * 8 + q));
                ex[q] = __expf(d[q] * a);
            }
            #pragma unroll
            for (int q = 0; q < 8; q++) {
                const int idx = sb * 8 + q;
                const float Bn = xsh[p][idx][R_ + n];
                const float Cn = xsh[p][idx][R_ + N_ + n];
                s = fmaf(s, ex[q], (d[q] * uv[q]) * Bn);
                v[q] = s * Cn;
            }
            #pragma unroll
            for (int q = 0; q < 8; q++) {
                v[q] += __shfl_xor_sync(0xffffffffu, v[q], 1);
                v[q] += __shfl_xor_sync(0xffffffffu, v[q], 2);
                v[q] += __shfl_xor_sync(0xffffffffu, v[q], 4);
                v[q] += __shfl_xor_sync(0xffffffffu, v[q], 8);
            }
            if (n == 0) {
                #pragma unroll
                for (int q = 0; q < 8; q++)
                    ybuf[p][sb * 8 + q][wl * 2 + half] = fmaf(uv[q], dp, v[q]);
            }
        }
        CP_WAIT0();
        __syncthreads();
        yblk[(size_t)(t0 + tl_st) * E_ + el_st] = ybuf[p][tl_st][el_st];
        p ^= 1;
    }
}

// ============ batch-sum + gate -> g_aug [hi|lo] ===============================
__global__ __launch_bounds__(256) void gate_kernel(
    const float4* __restrict__ y4, const float* __restrict__ xz,
    __nv_bfloat16* __restrict__ gaug)
{
    const int idx = blockIdx.x * blockDim.x + threadIdx.x;
    if (idx >= L_ * E_ / 4) return;
    float4 ss = make_float4(0.f, 0.f, 0.f, 0.f);
    #pragma unroll
    for (int b = 0; b < BATCH_; b++) {
        const float4 t = y4[(size_t)b * (L_ * E_ / 4) + idx];
        ss.x += t.x; ss.y += t.y; ss.z += t.z; ss.w += t.w;
    }
    const int p = idx * 4;
    const int t = p / E_;
    const int e = p - t * E_;
    #pragma unroll
    for (int b = 0; b < BATCH_; b++) {
        const float4 z4 = *reinterpret_cast<const float4*>(
            xz + ((size_t)(b * L_ + t)) * (2 * E_) + E_ + e);
        float v[4];
        v[0] = ss.x * z4.x / (1.f + __expf(-z4.x));
        v[1] = ss.y * z4.y / (1.f + __expf(-z4.y));
        v[2] = ss.z * z4.z / (1.f + __expf(-z4.z));
        v[3] = ss.w * z4.w / (1.f + __expf(-z4.w));
        uint32_t hiw[2], low[2];
        #pragma unroll
        for (int h = 0; h < 2; h++) {
            __nv_bfloat16 h0 = __float2bfloat16(v[2*h]);
            __nv_bfloat16 h1 = __float2bfloat16(v[2*h+1]);
            __nv_bfloat16 l0 = __float2bfloat16(v[2*h]   - __bfloat162float(h0));
            __nv_bfloat16 l1 = __float2bfloat16(v[2*h+1] - __bfloat162float(h1));
            hiw[h] = (uint32_t)__bfloat16_as_ushort(h0) |
                     ((uint32_t)__bfloat16_as_ushort(h1) << 16);
            low[h] = (uint32_t)__bfloat16_as_ushort(l0) |
                     ((uint32_t)__bfloat16_as_ushort(l1) << 16);
        }
        const size_t base = ((size_t)(b * L_ + t)) * (2 * E_) + e;
        *reinterpret_cast<uint2*>(&gaug[base])      = make_uint2(hiw[0], hiw[1]);
        *reinterpret_cast<uint2*>(&gaug[base + E_]) = make_uint2(low[0], low[1]);
    }
}

// ============ launch ==========================================================
extern "C" void kernel_launch(void* const* d_in, const int* in_sizes, int n_in,
                              void* d_out, int out_size)
{
    int base = 3;
    if (in_sizes[1] == 2 * E_ * DM_) base = 1;

    const float* x      = (const float*)d_in[0];
    const float* W_in   = (const float*)d_in[base + 0];
    const float* conv_w = (const float*)d_in[base + 1];
    const float* conv_b = (const float*)d_in[base + 2];
    const float* W_x    = (const float*)d_in[base + 3];
    const float* W_dt   = (const float*)d_in[base + 4];
    const float* b_dt   = (const float*)d_in[base + 5];
    const float* A_log  = (const float*)d_in[base + 6];
    const float* Dp     = (const float*)d_in[base + 7];
    const float* W_out  = (const float*)d_in[base + 8];
    float* out = (float*)d_out;

    float *xz, *ut, *xdbl, *y;
    __nv_bfloat16 *xaug, *uaug, *gaug, *wina, *wxa, *woa;
    cudaGetSymbolAddress((void**)&xz,    g_xz);
    cudaGetSymbolAddress((void**)&ut,    g_ut);
    cudaGetSymbolAddress((void**)&xdbl,  g_xdbl);
    cudaGetSymbolAddress((void**)&y,     g_y);
    cudaGetSymbolAddress((void**)&xaug,  g_xaug);
    cudaGetSymbolAddress((void**)&uaug,  g_uaug);
    cudaGetSymbolAddress((void**)&gaug,  g_gaug);
    cudaGetSymbolAddress((void**)&wina,  g_wina);
    cudaGetSymbolAddress((void**)&wxa,   g_wxa);
    cudaGetSymbolAddress((void**)&woa,   g_woa);

    // dynamic smem (LDS=40: 80B rows)
    const int sz128 = 3 * 128 * 40 * 2 + 3 * 128 * 40 * 2;  // 61440 (BN=128)
    const int sz96  = 3 * 128 * 40 * 2 + 3 *  96 * 40 * 2;  // 53760 (BN=96)
    const int sz64a = 3 * 128 * 40 * 2 + 3 *  64 * 40 * 2;  // 46080 (BN=64)
    const int sz64  = sz64a > 128 * 64 * 4 ? sz64a : 128 * 64 * 4;
    cudaFuncSetAttribute(wmma_gemm<128, 4, false>, cudaFuncAttributeMaxDynamicSharedMemorySize, sz128);
    cudaFuncSetAttribute(wmma_gemm<96, 4, false>,  cudaFuncAttributeMaxDynamicSharedMemorySize, sz96);
    cudaFuncSetAttribute(wmma_gemm<64, 8, true>,   cudaFuncAttributeMaxDynamicSharedMemorySize, sz64);

    // order: split(0), GEMM1(1), conv(2), GEMM3(3=profiled), scan(4), gate(5), GEMM7(6)
    split_all<<<SPLIT_B0 + SPLIT_B1 + SPLIT_B2 + SPLIT_B3, 256>>>(x, W_in, W_x, W_out);
    wmma_gemm<128, 4, false><<<dim3(6, ROWS_ / 128), 128, sz128>>>(
        xaug, wina, xz, 2 * E_, DM_, 2 * E_);
    dwconv_silu<<<dim3(3, 64, BATCH_), 128>>>(xz, conv_w, conv_b, ut, uaug);
    wmma_gemm<64, 8, true><<<dim3(1, ROWS_ / 128), 256, sz64>>>(
        uaug, wxa, xdbl, XD_, E_, XD_);
    scan_kernel<<<BATCH_ * (E_ / 2) / 4, 128>>>(ut, xdbl, W_dt, b_dt, A_log, Dp, y);
    gate_kernel<<<(L_ * E_ / 4 + 255) / 256, 256>>>(
        reinterpret_cast<const float4*>(y), xz, gaug);
    wmma_gemm<96, 4, false><<<dim3(2, ROWS_ / 128), 128, sz96>>>(
        gaug, woa, out, DM_, E_, DM_);
}

// round 16
// speedup vs baseline: 1.3881x; 1.0099x over previous
#include <cuda_runtime.h>
#include <cuda_bf16.h>
#include <mma.h>
#include <cstdint>

using namespace nvcuda;

#define BATCH_ 8
#define H_ 64
#define W_ 64
#define L_ 4096
#define DM_ 192
#define E_ 384
#define N_ 16
#define R_ 12
#define XD_ 44
#define ROWS_ (BATCH_*L_)

// ---------------- cp.async helpers ------------------------------------------
__device__ __forceinline__ uint32_t smem_u32(const void* p) {
    uint32_t a;
    asm("{ .reg .u64 t; cvta.to.shared.u64 t, %1; cvt.u32.u64 %0, t; }" : "=r"(a) : "l"(p));
    return a;
}
#define CP_ASYNC16(dst, src, szbytes) \
    asm volatile("cp.async.cg.shared.global [%0], [%1], 16, %2;" \
                 :: "r"(dst), "l"(src), "r"(szbytes))
#define CP_COMMIT() asm volatile("cp.async.commit_group;")
#define CP_WAIT1()  asm volatile("cp.async.wait_group 1;")
#define CP_WAIT0()  asm volatile("cp.async.wait_group 0;")

// ---------------- scratch ----------------------------------------------------
__device__ float g_xz   [(size_t)ROWS_ * 2 * E_];
__device__ float g_ut   [(size_t)ROWS_ * E_];
__device__ float g_xdbl [(size_t)ROWS_ * XD_];
__device__ float g_y    [(size_t)ROWS_ * E_];
__device__ __nv_bfloat16 g_xaug [(size_t)ROWS_ * 2 * DM_];
__device__ __nv_bfloat16 g_uaug [(size_t)ROWS_ * 2 * E_];
__device__ __nv_bfloat16 g_gaug [(size_t)ROWS_ * 2 * E_];
__device__ __nv_bfloat16 g_wina [(size_t)(2*E_) * 2 * DM_];
__device__ __nv_bfloat16 g_wxa  [(size_t)XD_ * 2 * E_];
__device__ __nv_bfloat16 g_woa  [(size_t)DM_ * 2 * E_];

// ---------- hi/lo split helpers -----------------------------------------------
__device__ __forceinline__ void split_one(const float* __restrict__ src,
                                          __nv_bfloat16* __restrict__ dst,
                                          int K, int idx, int nwork)
{
    if (idx >= nwork) return;
    int r = idx / (K / 2), kk = (idx - r * (K / 2)) * 2;
    const float2 v2 = *reinterpret_cast<const float2*>(src + (size_t)r * K + kk);
    __nv_bfloat16 h0 = __float2bfloat16(v2.x);
    __nv_bfloat16 h1 = __float2bfloat16(v2.y);
    __nv_bfloat16 l0 = __float2bfloat16(v2.x - __bfloat162float(h0));
    __nv_bfloat16 l1 = __float2bfloat16(v2.y - __bfloat162float(h1));
    uint32_t hw = (uint32_t)__bfloat16_as_ushort(h0) | ((uint32_t)__bfloat16_as_ushort(h1) << 16);
    uint32_t lw = (uint32_t)__bfloat16_as_ushort(l0) | ((uint32_t)__bfloat16_as_ushort(l1) << 16);
    size_t base = (size_t)r * 2 * K + kk;
    *reinterpret_cast<uint32_t*>(&dst[base])     = hw;
    *reinterpret_cast<uint32_t*>(&dst[base + K]) = lw;
}

#define SPLIT_N0 (ROWS_ * DM_ / 2)
#define SPLIT_N1 (2 * E_ * DM_ / 2)
#define SPLIT_N2 (XD_ * E_ / 2)
#define SPLIT_N3 (DM_ * E_ / 2)
#define SPLIT_B1 ((SPLIT_N1 + 255) / 256)
#define SPLIT_B2 ((SPLIT_N2 + 255) / 256)
#define SPLIT_B3 ((SPLIT_N3 + 255) / 256)

__global__ void split_x(const float* __restrict__ x)
{
    split_one(x, g_xaug, DM_, blockIdx.x * 256 + threadIdx.x, SPLIT_N0);
}

__global__ void split_w(const float* __restrict__ W_in, const float* __restrict__ W_x,
                        const float* __restrict__ W_out)
{
    int blk = blockIdx.x;
    if (blk < SPLIT_B1) {
        split_one(W_in, g_wina, DM_, blk * 256 + threadIdx.x, SPLIT_N1);
    } else if (blk < SPLIT_B1 + SPLIT_B2) {
        split_one(W_x, g_wxa, E_, (blk - SPLIT_B1) * 256 + threadIdx.x, SPLIT_N2);
    } else {
        split_one(W_out, g_woa, E_, (blk - SPLIT_B1 - SPLIT_B2) * 256 + threadIdx.x, SPLIT_N3);
    }
}

// ============ WMMA bf16 GEMM, logical Kaug=3*K0 over physical [hi|lo] ========
template<int BN, int NW, bool GUARDN>
__global__ __launch_bounds__(NW * 32, (NW == 4 ? 3 : 2)) void wmma_gemm(
    const __nv_bfloat16* __restrict__ Aaug,
    const __nv_bfloat16* __restrict__ Baug,
    float* __restrict__ C, int ldc, int K0, int Nout)
{
    constexpr int BM = 128, BK = 32;
    constexpr int THREADS = NW * 32;
    constexpr int WNC = BN / (NW / 2);
    constexpr int NFRW = WNC / 16;
    constexpr int LDS = BK + 8;
    constexpr int ABYTES = 3 * BM * LDS * 2;
    constexpr int AITER = (BM * 4) / THREADS;
    constexpr int BITER = (BN * 4) / THREADS;

    extern __shared__ __align__(32) char smem_raw[];
    typedef __nv_bfloat16 ARow[BM][LDS];
    typedef __nv_bfloat16 BRow[BN][LDS];
    ARow* sA = reinterpret_cast<ARow*>(smem_raw);
    BRow* sB = reinterpret_cast<BRow*>(smem_raw + ABYTES);

    const int tid  = threadIdx.x;
    const int wid  = tid >> 5;
    const int wy   = wid & 1;
    const int wx   = wid >> 1;
    const int row0 = blockIdx.y * BM;
    const int col0 = blockIdx.x * BN;
    const int strideAB = 2 * K0;

    wmma::fragment<wmma::accumulator, 16, 16, 16, float> acc[4][NFRW];
    #pragma unroll
    for (int i = 0; i < 4; i++)
        #pragma unroll
        for (int j = 0; j < NFRW; j++) wmma::fill_fragment(acc[i][j], 0.f);

    const int nk = (3 * K0) / BK;

    auto ld_tiles = [&](int kc, int buf) {
        const int p    = kc * BK;
        const int aOff = (p < 2 * K0) ? p : p - 2 * K0;
        const int bOff = (p < K0)     ? p : p - K0;
        #pragma unroll
        for (int it = 0; it < AITER; it++) {
            int idx = it * THREADS + tid;
            int r = idx >> 2, ck = idx & 3;
            const __nv_bfloat16* src = Aaug + (size_t)(row0 + r) * strideAB + aOff + ck * 8;
            CP_ASYNC16(smem_u32(&sA[buf][r][ck * 8]), src, 16);
        }
        #pragma unroll
        for (int it = 0; it < BITER; it++) {
            int idx = it * THREADS + tid;
            int r = idx >> 2, ck = idx & 3;
            int n = col0 + r;
            const __nv_bfloat16* src = Baug + (size_t)n * strideAB + bOff + ck * 8;
            CP_ASYNC16(smem_u32(&sB[buf][r][ck * 8]), src, (!GUARDN || n < Nout) ? 16 : 0);
        }
    };

    auto compute = [&](int buf) {
        #pragma unroll
        for (int ks = 0; ks < 2; ks++) {
            wmma::fragment<wmma::matrix_b, 16, 16, 16, __nv_bfloat16, wmma::col_major> bf[NFRW];
            #pragma unroll
            for (int j = 0; j < NFRW; j++)
                wmma::load_matrix_sync(bf[j], &sB[buf][wx * WNC + j * 16][ks * 16], LDS);
            #pragma unroll
            for (int i = 0; i < 4; i++) {
                wmma::fragment<wmma::matrix_a, 16, 16, 16, __nv_bfloat16, wmma::row_major> af;
                wmma::load_matrix_sync(af, &sA[buf][wy * 64 + i * 16][ks * 16], LDS);
                #pragma unroll
                for (int j = 0; j < NFRW; j++)
                    wmma::mma_sync(acc[i][j], af, bf[j], acc[i][j]);
            }
        }
    };

    ld_tiles(0, 0); CP_COMMIT();
    ld_tiles(1, 1); CP_COMMIT();

    for (int kt = 0; kt < nk; kt++) {
        const int buf = kt % 3;
        if (kt + 1 < nk) { CP_WAIT1(); } else { CP_WAIT0(); }
        __syncthreads();
        if (kt + 2 < nk) { ld_tiles(kt + 2, (kt + 2) % 3); CP_COMMIT(); }
        compute(buf);
    }

    if (!GUARDN) {
        #pragma unroll
        for (int i = 0; i < 4; i++)
            #pragma unroll
            for (int j = 0; j < NFRW; j++) {
                int cc = col0 + wx * WNC + j * 16;
                if (cc + 16 <= Nout)
                    wmma::store_matrix_sync(
                        C + (size_t)(row0 + wy * 64 + i * 16) * ldc + cc,
                        acc[i][j], ldc, wmma::mem_row_major);
            }
    } else {
        float* stage = reinterpret_cast<float*>(smem_raw);
        __syncthreads();
        #pragma unroll
        for (int i = 0; i < 4; i++)
            #pragma unroll
            for (int j = 0; j < NFRW; j++)
                wmma::store_matrix_sync(
                    stage + (size_t)(wy * 64 + i * 16) * BN + wx * WNC + j * 16,
                    acc[i][j], BN, wmma::mem_row_major);
        __syncthreads();
        for (int idx = tid; idx < BM * BN; idx += THREADS) {
            int r = idx / BN, c = idx - r * BN;
            if (col0 + c < Nout)
                C[(size_t)(row0 + r) * ldc + col0 + c] = stage[idx];
        }
    }
}

// ============ depthwise 7x7 conv + SiLU — sliding window, 16-row tiles ========
__global__ __launch_bounds__(128) void dwconv_silu(
    const float* __restrict__ xz, const float* __restrict__ cw,
    const float* __restrict__ cb, float* __restrict__ u_t,
    __nv_bfloat16* __restrict__ uaug)
{
    const int tid = threadIdx.x;
    const int e   = blockIdx.x * 128 + tid;
    const int ty0 = (blockIdx.y >> 3) * 16;       // 4 y-tiles of 16 rows
    const int tx0 = (blockIdx.y & 7) * 8;
    const int b   = blockIdx.z;

    __shared__ float wsh[128 * 49];
    for (int i = tid; i < 128 * 49; i += 128)
        wsh[i] = cw[(size_t)blockIdx.x * 128 * 49 + i];
    __syncthreads();
    float wr[49];
    #pragma unroll
    for (int j = 0; j < 49; j++) wr[j] = wsh[tid * 49 + j];
    const float bv = cb[e];

    float acc[7][8];
    #pragma unroll
    for (int j = 0; j < 7; j++)
        #pragma unroll
        for (int ox = 0; ox < 8; ox++) acc[j][ox] = bv;

    const size_t rowbase = (size_t)b * L_;
    float* utbase = u_t + ((size_t)b * E_ + e) * L_;

    #pragma unroll 1
    for (int iy = ty0 - 3; iy <= ty0 + 18; iy++) {
        if (iy >= 0 && iy < H_) {
            float row[14];
            const float* rp = xz + (rowbase + (size_t)iy * W_) * (2 * E_) + e;
            #pragma unroll
            for (int c = 0; c < 14; c++) {
                const int ix = tx0 + c - 3;
                row[c] = (ix >= 0 && ix < W_) ? rp[(size_t)ix * (2 * E_)] : 0.f;
            }
            #pragma unroll
            for (int ky = 0; ky < 7; ky++) {
                const int yy = iy + 3 - ky;
                if (yy >= ty0 && yy < ty0 + 16) {
                    #pragma unroll
                    for (int kx = 0; kx < 7; kx++) {
                        const float wv = wr[ky * 7 + kx];
                        #pragma unroll
                        for (int ox = 0; ox < 8; ox++)
                            acc[6 - ky][ox] = fmaf(row[ox + kx], wv, acc[6 - ky][ox]);
                    }
                }
            }
        }
        const int yy = iy - 3;
        if (yy >= ty0 && yy < ty0 + 16) {
            float v[8];
            #pragma unroll
            for (int ox = 0; ox < 8; ox++) {
                const float a0 = acc[0][ox];
                v[ox] = a0 / (1.f + __expf(-a0));
                const size_t row_t = rowbase + yy * W_ + tx0 + ox;
                __nv_bfloat16 hi = __float2bfloat16(v[ox]);
                __nv_bfloat16 lo = __float2bfloat16(v[ox] - __bfloat162float(hi));
                const size_t ab = row_t * (2 * E_) + e;
                uaug[ab] = hi; uaug[ab + E_] = lo;
            }
            float4* up = reinterpret_cast<float4*>(utbase + yy * W_ + tx0);
            up[0] = make_float4(v[0], v[1], v[2], v[3]);
            up[1] = make_float4(v[4], v[5], v[6], v[7]);
        }
        #pragma unroll
        for (int j = 0; j < 6; j++)
            #pragma unroll
            for (int ox = 0; ox < 8; ox++) acc[j][ox] = acc[j + 1][ox];
        #pragma unroll
        for (int ox = 0; ox < 8; ox++) acc[6][ox] = bv;
    }
}

// ============ selective scan — fused delta, cp.async-staged xdbl =============
#define XP_ 44
__global__ __launch_bounds__(128) void scan_kernel(
    const float* __restrict__ u_t,  const float* __restrict__ xdbl,
    const float* __restrict__ W_dt, const float* __restrict__ b_dt,
    const float* __restrict__ A_log, const float* __restrict__ Dp,
    float* __restrict__ y)
{
    __shared__ __align__(16) float xsh[2][16][XP_];
    __shared__ float ybuf[2][16][8];

    const int tid  = threadIdx.x;
    const int wl   = tid >> 5;
    const int lane = tid & 31;
    const int half = lane >> 4;
    const int n    = lane & 15;
    const int gw   = blockIdx.x * 4 + wl;
    const int b    = gw / (E_ / 2);
    const int e    = (gw % (E_ / 2)) * 2 + half;
    const int e0   = (blockIdx.x % 48) * 8;

    const float a  = -__expf(A_log[e * N_ + n]);
    const float dp = Dp[e];
    const float b2 = 2.f * b_dt[e];
    float wdt[R_];
    #pragma unroll
    for (int k = 0; k < R_; k++) wdt[k] = W_dt[e * R_ + k];
    float s = 0.f;

    const float* uptr = u_t  + ((size_t)b * E_ + e) * L_;
    const float* xrow = xdbl + (size_t)b * L_ * XD_;
    float* yblk = y + ((size_t)b * L_) * E_ + e0;

    const int tl_st = tid >> 3;
    const int el_st = tid & 7;

    auto stage = [&](int t0, int buf) {
        #pragma unroll
        for (int it = 0; it < 2; it++) {
            int idx = it * 128 + tid;
            if (idx < 176) {
                int rr = idx / 11, cc = idx - rr * 11;
                const float* src = xrow + (size_t)(t0 + rr) * XD_ + cc * 4;
                CP_ASYNC16(smem_u32(&xsh[buf][rr][cc * 4]), src, 16);
            }
        }
    };

    stage(0, 0); CP_COMMIT(); CP_WAIT0();
    __syncthreads();

    int p = 0;
    for (int c = 0; c < L_ / 16; c++) {
        const int t0 = c * 16;
        if (c + 1 < L_ / 16) { stage(t0 + 16, p ^ 1); CP_COMMIT(); }

        float dval = b2;
        #pragma unroll
        for (int k = 0; k < R_; k++) dval = fmaf(xsh[p][n][k], wdt[k], dval);
        const float dlt = (dval > 20.f) ? dval : log1pf(__expf(dval));

        #pragma unroll
        for (int sb = 0; sb < 2; sb++) {
            const int tb = t0 + sb * 8;
            float uv[8], v[8];
            #pragma unroll
            for (int h = 0; h < 2; h++) {
                const float4 u4 = *reinterpret_cast<const float4*>(uptr + tb + 4 * h);
                uv[4*h] = u4.x; uv[4*h+1] = u4.y; uv[4*h+2] = u4.z; uv[4*h+3] = u4.w;
            }
            float d[8], ex[8];
            #pragma unroll
            for (int q = 0; q < 8; q++) {
                d[q]  = __shfl_sync(0xffffffffu, dlt, (half << 4) | (sb * 8 + q));
                ex[q] = __expf(d[q] * a);
            }
            #pragma unroll
            for (int q = 0; q < 8; q++) {
                const int idx = sb * 8 + q;
                const float Bn = xsh[p][idx][R_ + n];
                const float Cn = xsh[p][idx][R_ + N_ + n];
                s = fmaf(s, ex[q], (d[q] * uv[q]) * Bn);
                v[q] = s * Cn;
            }
            #pragma unroll
            for (int q = 0; q < 8; q++) {
                v[q] += __shfl_xor_sync(0xffffffffu, v[q], 1);
                v[q] += __shfl_xor_sync(0xffffffffu, v[q], 2);
                v[q] += __shfl_xor_sync(0xffffffffu, v[q], 4);
                v[q] += __shfl_xor_sync(0xffffffffu, v[q], 8);
            }
            if (n == 0) {
                #pragma unroll
                for (int q = 0; q < 8; q++)
                    ybuf[p][sb * 8 + q][wl * 2 + half] = fmaf(uv[q], dp, v[q]);
            }
        }
        CP_WAIT0();
        __syncthreads();
        yblk[(size_t)(t0 + tl_st) * E_ + el_st] = ybuf[p][tl_st][el_st];
        p ^= 1;
    }
}

// ============ batch-sum + gate -> g_aug [hi|lo] ===============================
__global__ __launch_bounds__(256) void gate_kernel(
    const float4* __restrict__ y4, const float* __restrict__ xz,
    __nv_bfloat16* __restrict__ gaug)
{
    const int idx = blockIdx.x * blockDim.x + threadIdx.x;
    if (idx >= L_ * E_ / 4) return;
    float4 ss = make_float4(0.f, 0.f, 0.f, 0.f);
    #pragma unroll
    for (int b = 0; b < BATCH_; b++) {
        const float4 t = y4[(size_t)b * (L_ * E_ / 4) + idx];
        ss.x += t.x; ss.y += t.y; ss.z += t.z; ss.w += t.w;
    }
    const int p = idx * 4;
    const int t = p / E_;
    const int e = p - t * E_;
    #pragma unroll
    for (int b = 0; b < BATCH_; b++) {
        const float4 z4 = *reinterpret_cast<const float4*>(
            xz + ((size_t)(b * L_ + t)) * (2 * E_) + E_ + e);
        float v[4];
        v[0] = ss.x * z4.x / (1.f + __expf(-z4.x));
        v[1] = ss.y * z4.y / (1.f + __expf(-z4.y));
        v[2] = ss.z * z4.z / (1.f + __expf(-z4.z));
        v[3] = ss.w * z4.w / (1.f + __expf(-z4.w));
        uint32_t hiw[2], low[2];
        #pragma unroll
        for (int h = 0; h < 2; h++) {
            __nv_bfloat16 h0 = __float2bfloat16(v[2*h]);
            __nv_bfloat16 h1 = __float2bfloat16(v[2*h+1]);
            __nv_bfloat16 l0 = __float2bfloat16(v[2*h]   - __bfloat162float(h0));
            __nv_bfloat16 l1 = __float2bfloat16(v[2*h+1] - __bfloat162float(h1));
            hiw[h] = (uint32_t)__bfloat16_as_ushort(h0) |
                     ((uint32_t)__bfloat16_as_ushort(h1) << 16);
            low[h] = (uint32_t)__bfloat16_as_ushort(l0) |
                     ((uint32_t)__bfloat16_as_ushort(l1) << 16);
        }
        const size_t base = ((size_t)(b * L_ + t)) * (2 * E_) + e;
        *reinterpret_cast<uint2*>(&gaug[base])      = make_uint2(hiw[0], hiw[1]);
        *reinterpret_cast<uint2*>(&gaug[base + E_]) = make_uint2(low[0], low[1]);
    }
}

// ============ launch ==========================================================
extern "C" void kernel_launch(void* const* d_in, const int* in_sizes, int n_in,
                              void* d_out, int out_size)
{
    int base = 3;
    if (in_sizes[1] == 2 * E_ * DM_) base = 1;

    const float* x      = (const float*)d_in[0];
    const float* W_in   = (const float*)d_in[base + 0];
    const float* conv_w = (const float*)d_in[base + 1];
    const float* conv_b = (const float*)d_in[base + 2];
    const float* W_x    = (const float*)d_in[base + 3];
    const float* W_dt   = (const float*)d_in[base + 4];
    const float* b_dt   = (const float*)d_in[base + 5];
    const float* A_log  = (const float*)d_in[base + 6];
    const float* Dp     = (const float*)d_in[base + 7];
    const float* W_out  = (const float*)d_in[base + 8];
    float* out = (float*)d_out;

    float *xz, *ut, *xdbl, *y;
    __nv_bfloat16 *xaug, *uaug, *gaug, *wina, *wxa, *woa;
    cudaGetSymbolAddress((void**)&xz,    g_xz);
    cudaGetSymbolAddress((void**)&ut,    g_ut);
    cudaGetSymbolAddress((void**)&xdbl,  g_xdbl);
    cudaGetSymbolAddress((void**)&y,     g_y);
    cudaGetSymbolAddress((void**)&xaug,  g_xaug);
    cudaGetSymbolAddress((void**)&uaug,  g_uaug);
    cudaGetSymbolAddress((void**)&gaug,  g_gaug);
    cudaGetSymbolAddress((void**)&wina,  g_wina);
    cudaGetSymbolAddress((void**)&wxa,   g_wxa);
    cudaGetSymbolAddress((void**)&woa,   g_woa);

    const int sz128 = 3 * 128 * 40 * 2 + 3 * 128 * 40 * 2;
    const int sz96  = 3 * 128 * 40 * 2 + 3 *  96 * 40 * 2;
    const int sz64a = 3 * 128 * 40 * 2 + 3 *  64 * 40 * 2;
    const int sz64  = sz64a > 128 * 64 * 4 ? sz64a : 128 * 64 * 4;
    cudaFuncSetAttribute(wmma_gemm<128, 4, false>, cudaFuncAttributeMaxDynamicSharedMemorySize, sz128);
    cudaFuncSetAttribute(wmma_gemm<96, 4, false>,  cudaFuncAttributeMaxDynamicSharedMemorySize, sz96);
    cudaFuncSetAttribute(wmma_gemm<64, 8, true>,   cudaFuncAttributeMaxDynamicSharedMemorySize, sz64);

    // order: split_w(0), split_x(1), GEMM1(2), conv(3=profiled), GEMM3(4),
    //        scan(5), gate(6), GEMM7(7) — all producers precede consumers
    split_w<<<SPLIT_B1 + SPLIT_B2 + SPLIT_B3, 256>>>(W_in, W_x, W_out);
    split_x<<<(SPLIT_N0 + 255) / 256, 256>>>(x);
    wmma_gemm<128, 4, false><<<dim3(6, ROWS_ / 128), 128, sz128>>>(
        xaug, wina, xz, 2 * E_, DM_, 2 * E_);
    dwconv_silu<<<dim3(3, 32, BATCH_), 128>>>(xz, conv_w, conv_b, ut, uaug);
    wmma_gemm<64, 8, true><<<dim3(1, ROWS_ / 128), 256, sz64>>>(
        uaug, wxa, xdbl, XD_, E_, XD_);
    scan_kernel<<<BATCH_ * (E_ / 2) / 4, 128>>>(ut, xdbl, W_dt, b_dt, A_log, Dp, y);
    gate_kernel<<<(L_ * E_ / 4 + 255) / 256, 256>>>(
        reinterpret_cast<const float4*>(y), xz, gaug);
    wmma_gemm<96, 4, false><<<dim3(2, ROWS_ / 128), 128, sz96>>>(
        gaug, woa, out, DM_, E_, DM_);
}